// round 2
// baseline (speedup 1.0000x reference)
#include <cuda_runtime.h>
#include <cstdint>

// ---------------------------------------------------------------- problem dims
#define NDIRS   6
#define IDIM_   256
#define ODIM_   512
#define LSEQ    4096
#define NCHN    8192
#define NTOK    32768
#define KTOT    512
#define MTILE   128
#define KC      64                    // K per smem chunk
#define NKCH    8                     // K chunks (512/64)
#define NNB     4                     // n-blocks of 128
#define MAXTILES (NTOK / MTILE + NDIRS)   // 262

// ---------------------------------------------------------------- device scratch
__device__ float g_Wc[NDIRS * ODIM_ * KTOT];   // tf32-rounded weights, [d][n][k]
__device__ int   g_count[NDIRS];
__device__ int2  g_bucket[NDIRS * NTOK];       // (.x = token id, .y = c0 | c1<<16)

// ---------------------------------------------------------------- helpers (base-ISA only)
__device__ __forceinline__ uint32_t smem_u32(const void* p) {
    uint32_t a;
    asm("{ .reg .u64 t; cvta.to.shared.u64 t, %1; cvt.u32.u64 %0, t; }" : "=r"(a) : "l"(p));
    return a;
}

__device__ __forceinline__ float f2tf32(float x) {
    uint32_t u;
    asm("cvt.rna.tf32.f32 %0, %1;" : "=r"(u) : "f"(x));
    return __uint_as_float(u);
}

__device__ __forceinline__ void cp16(uint32_t dst, const void* src) {
    asm volatile("cp.async.cg.shared.global [%0], [%1], 16;\n"
                 :: "r"(dst), "l"(src) : "memory");
}
#define CP_COMMIT() asm volatile("cp.async.commit_group;\n" ::: "memory")
#define CP_WAIT0()  asm volatile("cp.async.wait_group 0;\n" ::: "memory")

__device__ __forceinline__ void mma8(float* c, const uint32_t* a, const uint32_t* b) {
    asm volatile(
        "mma.sync.aligned.m16n8k8.row.col.f32.tf32.tf32.f32 "
        "{%0,%1,%2,%3}, {%4,%5,%6,%7}, {%8,%9}, {%0,%1,%2,%3};\n"
        : "+f"(c[0]), "+f"(c[1]), "+f"(c[2]), "+f"(c[3])
        : "r"(a[0]), "r"(a[1]), "r"(a[2]), "r"(a[3]), "r"(b[0]), "r"(b[1]));
}

// ---------------------------------------------------------------- K0: W -> tf32 + zero counts
__global__ void k_prep(const float* __restrict__ W) {
    int i = blockIdx.x * blockDim.x + threadIdx.x;
    if (blockIdx.x == 0 && threadIdx.x < NDIRS) g_count[threadIdx.x] = 0;
    if (i < NDIRS * ODIM_ * KTOT) g_Wc[i] = f2tf32(W[i]);
}

// ---------------------------------------------------------------- K1: bucket tokens by dir
__global__ void k_bucket(const int* __restrict__ child_l, const int* __restrict__ child_r,
                         const int* __restrict__ vec, const int* __restrict__ drev,
                         const int* __restrict__ dmap) {
    int t = blockIdx.x * blockDim.x + threadIdx.x;
    int l = t & (LSEQ - 1);
    int v = vec[t];
    int dir = dmap[v];
    int d = drev[v];
    int cl = child_l[l], cr = child_r[l];
    int c0 = d ? cr : cl;
    int c1 = d ? cl : cr;
    int payload = c0 | (c1 << 16);
    int lane = threadIdx.x & 31;

    #pragma unroll
    for (int dd = 0; dd < NDIRS; dd++) {
        unsigned mask = __ballot_sync(0xFFFFFFFFu, dir == dd);
        if (dir == dd) {
            int leader = __ffs(mask) - 1;
            int base = 0;
            if (lane == leader) base = atomicAdd(&g_count[dd], __popc(mask));
            base = __shfl_sync(mask, base, leader);
            int pos = base + __popc(mask & ((1u << lane) - 1u));
            g_bucket[dd * NTOK + pos] = make_int2(t, payload);
        }
    }
}

// ---------------------------------------------------------------- K2: bucketed tf32 GEMM (mma.sync)
// SMEM: rowTok[128] @0, rs0[128] @512, rs1[128] @1024, bias[512] @1536,
//       stages @4096: each stage = A[128][68] + B[128][68] floats.
#define STRIDE     68
#define A_FLOATS   (128 * STRIDE)          // 8704
#define STAGE_FLOATS (2 * A_FLOATS)        // 17408
#define STAGE_BYTES (STAGE_FLOATS * 4)     // 69632
#define SM_ROWTOK  0
#define SM_ROWS0   512
#define SM_ROWS1   1024
#define SM_BIAS    1536
#define SM_STAGE   4096
#define SMEM_DYN   (SM_STAGE + 2 * STAGE_BYTES)   // 143360

__global__ void __launch_bounds__(256, 1) k_gemm(
    const float* __restrict__ last,
    const float* __restrict__ b_merge,
    const float* __restrict__ alpha_merge,
    float* __restrict__ out)
{
    extern __shared__ char smp[];
    const uint32_t sbase = smem_u32(smp);

    const int tid = threadIdx.x;
    const int wid = tid >> 5;
    const int lid = tid & 31;

    // ---- map CTA -> (dir, tile)
    int dir = -1, tile = 0;
    {
        int acc = 0;
        #pragma unroll
        for (int d = 0; d < NDIRS; d++) {
            int nt = (g_count[d] + MTILE - 1) >> 7;
            if (dir < 0 && (int)blockIdx.x < acc + nt) { dir = d; tile = blockIdx.x - acc; }
            acc += nt;
        }
    }
    if (dir < 0) return;
    const int count = g_count[dir];
    const int rowbase = tile * MTILE;

    // ---- metadata
    if (tid < MTILE) {
        int idx = rowbase + tid;
        int2 e = (idx < count) ? g_bucket[dir * NTOK + idx] : make_int2(0, 0);
        ((int*)(smp + SM_ROWTOK))[tid] = (idx < count) ? e.x : -1;
        int c0 = e.y & 0xFFFF;
        int c1 = (e.y >> 16) & 0xFFFF;
        int b = e.x >> 12;                  // token / LSEQ
        ((int*)(smp + SM_ROWS0))[tid] = b * NCHN + c0;
        ((int*)(smp + SM_ROWS1))[tid] = b * NCHN + c1;
    }
    for (int i = tid; i < ODIM_; i += 256)
        ((float*)(smp + SM_BIAS))[i] = b_merge[dir * ODIM_ + i];
    const float alpha = alpha_merge[dir];
    __syncthreads();

    const float* __restrict__ Wd = g_Wc + (size_t)dir * ODIM_ * KTOT;
    const int* rs0 = (const int*)(smp + SM_ROWS0);
    const int* rs1 = (const int*)(smp + SM_ROWS1);
    const int* rowTok = (const int*)(smp + SM_ROWTOK);
    const float* bias = (const float*)(smp + SM_BIAS);

    const int wm = wid & 3;       // M quadrant (32 rows)
    const int wn = wid >> 2;      // N half (64 cols)
    const int g  = lid >> 2;      // group id
    const int tig = lid & 3;      // thread in group

    for (int nb = 0; nb < NNB; nb++) {
        float acc[2][8][4];
        #pragma unroll
        for (int t = 0; t < 2; t++)
            #pragma unroll
            for (int j = 0; j < 8; j++)
                #pragma unroll
                for (int q = 0; q < 4; q++) acc[t][j][q] = 0.f;

        // ---- preload chunk 0 into stage 0
        {
            uint32_t Bsu = sbase + SM_STAGE + A_FLOATS * 4;
            #pragma unroll
            for (int i = 0; i < 8; i++) {
                int e = tid + i * 256; int n = e >> 4, q = e & 15;
                cp16(Bsu + (uint32_t)(n * STRIDE + q * 4) * 4,
                     Wd + (size_t)(nb * 128 + n) * KTOT + q * 4);
            }
            CP_COMMIT();
            float* As = (float*)(smp + SM_STAGE);
            #pragma unroll
            for (int i = 0; i < 8; i++) {
                int e = tid + i * 256; int r = e >> 4, q = e & 15;
                float4 v = *(const float4*)(last + (size_t)rs0[r] * IDIM_ + q * 4);
                v.x = f2tf32(v.x); v.y = f2tf32(v.y); v.z = f2tf32(v.z); v.w = f2tf32(v.w);
                *(float4*)(As + r * STRIDE + q * 4) = v;
            }
            CP_WAIT0();
            __syncthreads();
        }

        for (int c = 0; c < NKCH; c++) {
            const int s = c & 1;
            float4 apf[8];

            if (c < NKCH - 1) {
                const int s2 = s ^ 1;
                const int c2 = c + 1;
                uint32_t Bsu = sbase + SM_STAGE + (uint32_t)s2 * STAGE_BYTES + A_FLOATS * 4;
                #pragma unroll
                for (int i = 0; i < 8; i++) {
                    int e = tid + i * 256; int n = e >> 4, q = e & 15;
                    cp16(Bsu + (uint32_t)(n * STRIDE + q * 4) * 4,
                         Wd + (size_t)(nb * 128 + n) * KTOT + c2 * KC + q * 4);
                }
                CP_COMMIT();
                const int* rs = (c2 < 4) ? rs0 : rs1;
                const int kb = (c2 & 3) * KC;
                #pragma unroll
                for (int i = 0; i < 8; i++) {
                    int e = tid + i * 256; int r = e >> 4, q = e & 15;
                    apf[i] = *(const float4*)(last + (size_t)rs[r] * IDIM_ + kb + q * 4);
                }
            }

            // ---- compute chunk c from stage s
            const float* As = (const float*)(smp + SM_STAGE + (size_t)s * STAGE_BYTES);
            const float* Bs = As + A_FLOATS;
            #pragma unroll
            for (int kk = 0; kk < 8; kk++) {
                uint32_t af[2][4], bf[8][2];
                #pragma unroll
                for (int t = 0; t < 2; t++) {
                    const float* p = As + (wm * 32 + t * 16 + g) * STRIDE + kk * 8 + tig;
                    af[t][0] = __float_as_uint(p[0]);
                    af[t][1] = __float_as_uint(p[8 * STRIDE]);
                    af[t][2] = __float_as_uint(p[4]);
                    af[t][3] = __float_as_uint(p[8 * STRIDE + 4]);
                }
                #pragma unroll
                for (int j = 0; j < 8; j++) {
                    const float* p = Bs + (wn * 64 + j * 8 + g) * STRIDE + kk * 8 + tig;
                    bf[j][0] = __float_as_uint(p[0]);
                    bf[j][1] = __float_as_uint(p[4]);
                }
                #pragma unroll
                for (int t = 0; t < 2; t++)
                    #pragma unroll
                    for (int j = 0; j < 8; j++)
                        mma8(acc[t][j], af[t], bf[j]);
            }

            if (c < NKCH - 1) {
                const int s2 = s ^ 1;
                float* A2 = (float*)(smp + SM_STAGE + (size_t)s2 * STAGE_BYTES);
                #pragma unroll
                for (int i = 0; i < 8; i++) {
                    int e = tid + i * 256; int r = e >> 4, q = e & 15;
                    float4 v = apf[i];
                    v.x = f2tf32(v.x); v.y = f2tf32(v.y); v.z = f2tf32(v.z); v.w = f2tf32(v.w);
                    *(float4*)(A2 + r * STRIDE + q * 4) = v;
                }
                CP_WAIT0();
                __syncthreads();
            }
        }

        // ---- epilogue for this n-block (registers -> gmem)
        #pragma unroll
        for (int t = 0; t < 2; t++) {
            #pragma unroll
            for (int half = 0; half < 2; half++) {
                int r = wm * 32 + t * 16 + g + half * 8;
                int tok = rowTok[r];
                if (tok >= 0) {
                    float* op = out + (size_t)tok * ODIM_ + nb * 128 + wn * 64;
                    #pragma unroll
                    for (int j = 0; j < 8; j++) {
                        int colb = j * 8 + 2 * tig;
                        float y0 = acc[t][j][half * 2 + 0] + bias[nb * 128 + wn * 64 + colb];
                        float y1 = acc[t][j][half * 2 + 1] + bias[nb * 128 + wn * 64 + colb + 1];
                        float2 v;
                        v.x = y0 > 0.f ? y0 : alpha * y0;
                        v.y = y1 > 0.f ? y1 : alpha * y1;
                        *(float2*)(op + colb) = v;
                    }
                }
            }
        }
        // next nb's preload only touches stage0 while any laggard computes on
        // stage1, and preload ends with a syncthreads — no extra barrier needed.
    }
}

// ---------------------------------------------------------------- launch
extern "C" void kernel_launch(void* const* d_in, const int* in_sizes, int n_in,
                              void* d_out, int out_size) {
    const float* last  = (const float*)d_in[0];
    const float* W     = (const float*)d_in[1];
    const float* bm    = (const float*)d_in[2];
    const float* am    = (const float*)d_in[3];
    const int*   cl    = (const int*)d_in[4];
    const int*   cr    = (const int*)d_in[5];
    const int*   vec   = (const int*)d_in[6];
    const int*   drev  = (const int*)d_in[7];
    const int*   dmap  = (const int*)d_in[8];
    float*       out   = (float*)d_out;

    (void)in_sizes; (void)n_in; (void)out_size;

    static bool attr_done = false;
    if (!attr_done) {
        cudaFuncSetAttribute(k_gemm, cudaFuncAttributeMaxDynamicSharedMemorySize, SMEM_DYN);
        attr_done = true;
    }

    k_prep<<<(NDIRS * ODIM_ * KTOT + 255) / 256, 256>>>(W);
    k_bucket<<<NTOK / 256, 256>>>(cl, cr, vec, drev, dmap);
    k_gemm<<<MAXTILES, 256, SMEM_DYN>>>(last, bm, am, out);
}

// round 5
// speedup vs baseline: 1.4050x; 1.4050x over previous
#include <cuda_runtime.h>
#include <cstdint>

// ---------------------------------------------------------------- problem dims
#define NDIRS   6
#define IDIM_   256
#define ODIM_   512
#define LSEQ    4096
#define NCHN    8192
#define NTOK    32768
#define KTOT    512
#define MTILE   128
#define KC      32                    // K per smem chunk
#define NKCH    16                    // K chunks (512/32)
#define NNB     4                     // n-blocks of 128
#define MAXTILES (NTOK / MTILE + NDIRS)   // 262

// B packed block: per (dir, nb, kchunk): 4 kk * 4 tig * 1056B rows = 16896B
#define BBLK_BYTES   16896
#define BBLK_FLOATS  4224
#define BROW_BYTES   1056             // 128 cols * 8B + 32B pad
#define BROW_FLOATS  264
#define BKK_FLOATS   1056             // 4 tig rows

// A smem: 128 rows * 36 floats (stride 36 => conflict-free scalar frag loads)
#define A_STRIDE     36
#define A_BYTES      (128 * A_STRIDE * 4)     // 18432
#define STAGE_BYTES  (A_BYTES + BBLK_BYTES)   // 35328
#define SM_ROWTOK    0
#define SM_ROWS0     512
#define SM_ROWS1     1024
#define SM_STAGE     2048
#define SMEM_DYN     (SM_STAGE + 2 * STAGE_BYTES)   // 72704

// ---------------------------------------------------------------- device scratch
__device__ float g_Wp[NDIRS * NNB * NKCH * BBLK_FLOATS];  // fragment-packed tf32 W
__device__ int   g_count[NDIRS];
__device__ int2  g_bucket[NDIRS * NTOK];

// ---------------------------------------------------------------- helpers
__device__ __forceinline__ uint32_t smem_u32(const void* p) {
    uint32_t a;
    asm("{ .reg .u64 t; cvta.to.shared.u64 t, %1; cvt.u32.u64 %0, t; }" : "=r"(a) : "l"(p));
    return a;
}
__device__ __forceinline__ float f2tf32(float x) {
    uint32_t u;
    asm("cvt.rna.tf32.f32 %0, %1;" : "=r"(u) : "f"(x));
    return __uint_as_float(u);
}
__device__ __forceinline__ void cp16(uint32_t dst, const void* src) {
    asm volatile("cp.async.cg.shared.global [%0], [%1], 16;\n" :: "r"(dst), "l"(src) : "memory");
}
#define CP_COMMIT() asm volatile("cp.async.commit_group;\n" ::: "memory")
#define CP_WAIT0()  asm volatile("cp.async.wait_group 0;\n" ::: "memory")

__device__ __forceinline__ void mma8(float* c, const uint32_t* a, const uint32_t* b) {
    asm volatile(
        "mma.sync.aligned.m16n8k8.row.col.f32.tf32.tf32.f32 "
        "{%0,%1,%2,%3}, {%4,%5,%6,%7}, {%8,%9}, {%0,%1,%2,%3};\n"
        : "+f"(c[0]), "+f"(c[1]), "+f"(c[2]), "+f"(c[3])
        : "r"(a[0]), "r"(a[1]), "r"(a[2]), "r"(a[3]), "r"(b[0]), "r"(b[1]));
}

// ---------------------------------------------------------------- K0: pack W -> fragment layout (tf32 rna)
// grid = 384 blocks (d*4+nb)*16+ch, 128 threads. Each block packs one 128n x 32k tile.
__global__ void k_prep(const float* __restrict__ W) {
    int b = blockIdx.x;
    int ch = b & 15;
    int nb = (b >> 4) & 3;
    int d  = b >> 6;
    if (b == 0 && threadIdx.x < NDIRS) g_count[threadIdx.x] = 0;

    __shared__ float tile[128][33];
    int tid = threadIdx.x;

    #pragma unroll
    for (int i = 0; i < 8; i++) {
        int u = tid + i * 128;                 // 1024 float4 units
        int col = u >> 3, q = u & 7;
        const float* src = W + ((size_t)(d * ODIM_ + nb * 128 + col)) * KTOT + ch * KC + q * 4;
        float4 v = *(const float4*)src;
        tile[col][q * 4 + 0] = f2tf32(v.x);
        tile[col][q * 4 + 1] = f2tf32(v.y);
        tile[col][q * 4 + 2] = f2tf32(v.z);
        tile[col][q * 4 + 3] = f2tf32(v.w);
    }
    __syncthreads();

    float* dst = g_Wp + (size_t)b * BBLK_FLOATS;
    #pragma unroll
    for (int i = 0; i < 17; i++) {
        int u = tid + i * 128;                 // float2 units, 2112 total (incl pad)
        if (u >= 2112) break;
        int kk = u / 528;
        int r  = u - kk * 528;
        int tg = r / 132;
        int cc = r - tg * 132;
        float2 v = make_float2(0.f, 0.f);
        if (cc < 128) { v.x = tile[cc][kk * 8 + tg]; v.y = tile[cc][kk * 8 + tg + 4]; }
        *(float2*)(dst + kk * BKK_FLOATS + tg * BROW_FLOATS + cc * 2) = v;
    }
}

// ---------------------------------------------------------------- K1: bucket tokens by dir
__global__ void k_bucket(const int* __restrict__ child_l, const int* __restrict__ child_r,
                         const int* __restrict__ vec, const int* __restrict__ drev,
                         const int* __restrict__ dmap) {
    int t = blockIdx.x * blockDim.x + threadIdx.x;
    int l = t & (LSEQ - 1);
    int v = vec[t];
    int dir = dmap[v];
    int d = drev[v];
    int cl = child_l[l], cr = child_r[l];
    int c0 = d ? cr : cl;
    int c1 = d ? cl : cr;
    int payload = c0 | (c1 << 16);
    int lane = threadIdx.x & 31;

    #pragma unroll
    for (int dd = 0; dd < NDIRS; dd++) {
        unsigned mask = __ballot_sync(0xFFFFFFFFu, dir == dd);
        if (dir == dd) {
            int leader = __ffs(mask) - 1;
            int base = 0;
            if (lane == leader) base = atomicAdd(&g_count[dd], __popc(mask));
            base = __shfl_sync(mask, base, leader);
            int pos = base + __popc(mask & ((1u << lane) - 1u));
            g_bucket[dd * NTOK + pos] = make_int2(t, payload);
        }
    }
}

// ---------------------------------------------------------------- K2: bucketed tf32 GEMM
// 128 threads = 4 warps, warp tile m64 x n64, CTA tile 128 x 128 per n-block.
__global__ void __launch_bounds__(128, 2) k_gemm(
    const float* __restrict__ last,
    const float* __restrict__ b_merge,
    const float* __restrict__ alpha_merge,
    float* __restrict__ out)
{
    extern __shared__ char smp[];
    const uint32_t sbase = smem_u32(smp);

    const int tid = threadIdx.x;
    const int wid = tid >> 5;
    const int lid = tid & 31;
    const int wm = wid & 1;       // M half (64 rows)
    const int wn = wid >> 1;      // N half (64 cols)
    const int g   = lid >> 2;     // group (0..7)
    const int tig = lid & 3;      // thread-in-group (0..3)

    // ---- map CTA -> (dir, tile)
    int dir = -1, tile = 0;
    {
        int acc = 0;
        #pragma unroll
        for (int d = 0; d < NDIRS; d++) {
            int nt = (g_count[d] + MTILE - 1) >> 7;
            if (dir < 0 && (int)blockIdx.x < acc + nt) { dir = d; tile = blockIdx.x - acc; }
            acc += nt;
        }
    }
    if (dir < 0) return;
    const int count = g_count[dir];
    const int rowbase = tile * MTILE;

    // ---- row metadata (128 threads cover 128 rows)
    {
        int idx = rowbase + tid;
        int2 e = (idx < count) ? g_bucket[dir * NTOK + idx] : make_int2(0, 0);
        ((int*)(smp + SM_ROWTOK))[tid] = (idx < count) ? e.x : -1;
        int c0 = e.y & 0xFFFF;
        int c1 = (e.y >> 16) & 0xFFFF;
        int bb = e.x >> 12;                 // token / LSEQ
        ((int*)(smp + SM_ROWS0))[tid] = bb * NCHN + c0;
        ((int*)(smp + SM_ROWS1))[tid] = bb * NCHN + c1;
    }
    const float alpha = alpha_merge[dir];
    __syncthreads();

    const int* rs0 = (const int*)(smp + SM_ROWS0);
    const int* rs1 = (const int*)(smp + SM_ROWS1);
    const int* rowTok = (const int*)(smp + SM_ROWTOK);
    const float* __restrict__ Wp0 = g_Wp + (size_t)(dir * NNB) * NKCH * BBLK_FLOATS;

    for (int nb = 0; nb < NNB; nb++) {
        float acc[4][8][4];
        #pragma unroll
        for (int t = 0; t < 4; t++)
            #pragma unroll
            for (int j = 0; j < 8; j++)
                #pragma unroll
                for (int q = 0; q < 4; q++) acc[t][j][q] = 0.f;

        const float* __restrict__ Wpn = Wp0 + (size_t)nb * NKCH * BBLK_FLOATS;

        // ---- preload chunk 0 into stage 0
        {
            uint32_t adst = sbase + SM_STAGE;
            uint32_t bdst = adst + A_BYTES;
            const float* bsrc = Wpn;
            #pragma unroll
            for (int i = 0; i < 8; i++) {
                int u = tid + i * 128;
                cp16(bdst + u * 16, bsrc + u * 4);
            }
            { int u = tid + 1024; if (u < 1056) cp16(bdst + u * 16, bsrc + u * 4); }
            #pragma unroll
            for (int i = 0; i < 8; i++) {
                int e = tid + i * 128;         // 1024 16B units: 128 rows x 8 quads
                int row = e >> 3, q = e & 7;
                cp16(adst + row * (A_STRIDE * 4) + q * 16,
                     last + (size_t)rs0[row] * IDIM_ + q * 4);
            }
            CP_COMMIT();
            CP_WAIT0();
            __syncthreads();
        }

        for (int c = 0; c < NKCH; c++) {
            const int s = c & 1;

            if (c < NKCH - 1) {
                const int c2 = c + 1;
                uint32_t adst = sbase + SM_STAGE + (s ^ 1) * STAGE_BYTES;
                uint32_t bdst = adst + A_BYTES;
                const float* bsrc = Wpn + (size_t)c2 * BBLK_FLOATS;
                #pragma unroll
                for (int i = 0; i < 8; i++) {
                    int u = tid + i * 128;
                    cp16(bdst + u * 16, bsrc + u * 4);
                }
                { int u = tid + 1024; if (u < 1056) cp16(bdst + u * 16, bsrc + u * 4); }
                const int* rs = (c2 < 8) ? rs0 : rs1;
                const int koff = (c2 & 7) * KC;
                #pragma unroll
                for (int i = 0; i < 8; i++) {
                    int e = tid + i * 128;     // 1024 16B units: 128 rows x 8 quads
                    int row = e >> 3, q = e & 7;
                    cp16(adst + row * (A_STRIDE * 4) + q * 16,
                         last + (size_t)rs[row] * IDIM_ + koff + q * 4);
                }
                CP_COMMIT();
            }

            // ---- compute chunk c from stage s
            const float* As = (const float*)(smp + SM_STAGE + s * STAGE_BYTES);
            const char*  Bs = smp + SM_STAGE + s * STAGE_BYTES + A_BYTES;
            #pragma unroll
            for (int kk = 0; kk < 4; kk++) {
                uint32_t af[4][4];
                uint32_t bf[8][2];
                #pragma unroll
                for (int t = 0; t < 4; t++) {
                    const float* p = As + (wm * 64 + t * 16 + g) * A_STRIDE + kk * 8 + tig;
                    af[t][0] = __float_as_uint(p[0]);
                    af[t][1] = __float_as_uint(p[8 * A_STRIDE]);
                    af[t][2] = __float_as_uint(p[4]);
                    af[t][3] = __float_as_uint(p[8 * A_STRIDE + 4]);
                }
                #pragma unroll
                for (int j = 0; j < 8; j++) {
                    float2 v = *(const float2*)(Bs + kk * (BKK_FLOATS * 4) + tig * BROW_BYTES
                                                + (wn * 64 + j * 8 + g) * 8);
                    bf[j][0] = __float_as_uint(v.x);
                    bf[j][1] = __float_as_uint(v.y);
                }
                #pragma unroll
                for (int t = 0; t < 4; t++)
                    #pragma unroll
                    for (int j = 0; j < 8; j++)
                        mma8(acc[t][j], af[t], bf[j]);
            }

            if (c < NKCH - 1) {
                CP_WAIT0();
                __syncthreads();
            }
        }

        // ---- epilogue for this n-block
        {
            const float* bm = b_merge + dir * ODIM_ + nb * 128 + wn * 64;
            float2 bb[8];
            #pragma unroll
            for (int j = 0; j < 8; j++) bb[j] = *(const float2*)(bm + j * 8 + 2 * tig);
            #pragma unroll
            for (int t = 0; t < 4; t++) {
                #pragma unroll
                for (int h = 0; h < 2; h++) {
                    int r = wm * 64 + t * 16 + h * 8 + g;
                    int tok = rowTok[r];
                    if (tok >= 0) {
                        float* op = out + (size_t)tok * ODIM_ + nb * 128 + wn * 64;
                        #pragma unroll
                        for (int j = 0; j < 8; j++) {
                            float y0 = acc[t][j][h * 2 + 0] + bb[j].x;
                            float y1 = acc[t][j][h * 2 + 1] + bb[j].y;
                            float2 v;
                            v.x = y0 > 0.f ? y0 : alpha * y0;
                            v.y = y1 > 0.f ? y1 : alpha * y1;
                            *(float2*)(op + j * 8 + 2 * tig) = v;
                        }
                    }
                }
            }
        }
        // next nb's preload targets stage0; all warps finished stage0 compute
        // two chunks ago and the preload ends with CP_WAIT0 + __syncthreads.
    }
}

// ---------------------------------------------------------------- launch
extern "C" void kernel_launch(void* const* d_in, const int* in_sizes, int n_in,
                              void* d_out, int out_size) {
    const float* last  = (const float*)d_in[0];
    const float* W     = (const float*)d_in[1];
    const float* bm    = (const float*)d_in[2];
    const float* am    = (const float*)d_in[3];
    const int*   cl    = (const int*)d_in[4];
    const int*   cr    = (const int*)d_in[5];
    const int*   vec   = (const int*)d_in[6];
    const int*   drev  = (const int*)d_in[7];
    const int*   dmap  = (const int*)d_in[8];
    float*       out   = (float*)d_out;

    (void)in_sizes; (void)n_in; (void)out_size;

    static bool attr_done = false;
    if (!attr_done) {
        cudaFuncSetAttribute(k_gemm, cudaFuncAttributeMaxDynamicSharedMemorySize, SMEM_DYN);
        attr_done = true;
    }

    k_prep<<<NDIRS * NNB * NKCH, 128>>>(W);
    k_bucket<<<NTOK / 256, 256>>>(cl, cr, vec, drev, dmap);
    k_gemm<<<MAXTILES, 128, SMEM_DYN>>>(last, bm, am, out);
}